// round 1
// baseline (speedup 1.0000x reference)
#include <cuda_runtime.h>
#include <cuda_bf16.h>

#define BB 8
#define CC 512
#define C8 64
#define S  128
#define SS (S*S)
#define NEG_INF_F (-1000000000.0f)

// ---------------- scratch buffers (device globals; no allocation) ----------------
__device__ float g_q   [BB * C8 * SS];   //  32 MB  q[b][o][w][h]
__device__ float g_k   [BB * C8 * SS];   //  32 MB
__device__ float g_qT  [BB * C8 * SS];   //  32 MB  qT[b][o][h][w]
__device__ float g_kT  [BB * C8 * SS];   //  32 MB
__device__ float g_v   [BB * CC * SS];   // 256 MB  v[b][c][w][h]
__device__ float g_vT  [BB * CC * SS];   // 256 MB  vT[b][c][h][w]
__device__ float g_att [BB * SS * 2 * S];// 128 MB  att[b][w][h][0:256] (col|row)
__device__ float g_ocolT[BB * CC * SS];  // 256 MB  ocolT[b][c][h][w]

// ---------------- K1: fused QKV projection GEMM --------------------------------
// Per batch: [Wq;Wk;Wv](640x512) @ x[b](512x16384). 64x64 tile, BK=16, 4x4/thread.
__global__ void qkv_gemm(const float* __restrict__ x,
                         const float* __restrict__ Wq, const float* __restrict__ bq,
                         const float* __restrict__ Wk, const float* __restrict__ bk,
                         const float* __restrict__ Wv, const float* __restrict__ bv) {
    const int b  = blockIdx.z;
    const int M0 = blockIdx.y * 64;
    const int N0 = blockIdx.x * 64;
    const int tid = threadIdx.x;
    const int tx = tid & 15, ty = tid >> 4;

    __shared__ float As[16][64];
    __shared__ float Bs[16][64];

    float acc[4][4] = {};
    const float* xb = x + (size_t)b * CC * SS;

    for (int k0 = 0; k0 < CC; k0 += 16) {
        #pragma unroll
        for (int l = 0; l < 4; l++) {
            int idx = tid + l * 256;     // 0..1023
            int mp  = idx >> 4;
            int kk  = idx & 15;
            int m   = M0 + mp;
            int c   = k0 + kk;
            float val;
            if (m < 64)       val = Wq[m * CC + c];
            else if (m < 128) val = Wk[(m - 64) * CC + c];
            else              val = Wv[(m - 128) * CC + c];
            As[kk][mp] = val;
        }
        #pragma unroll
        for (int l = 0; l < 4; l++) {
            int idx = tid + l * 256;
            int kk  = idx >> 6;
            int np  = idx & 63;
            Bs[kk][np] = xb[(size_t)(k0 + kk) * SS + N0 + np];
        }
        __syncthreads();
        #pragma unroll
        for (int kk = 0; kk < 16; kk++) {
            float a[4], bv4[4];
            #pragma unroll
            for (int i = 0; i < 4; i++) a[i]   = As[kk][ty * 4 + i];
            #pragma unroll
            for (int j = 0; j < 4; j++) bv4[j] = Bs[kk][tx * 4 + j];
            #pragma unroll
            for (int i = 0; i < 4; i++)
                #pragma unroll
                for (int j = 0; j < 4; j++)
                    acc[i][j] = fmaf(a[i], bv4[j], acc[i][j]);
        }
        __syncthreads();
    }

    const int n0 = N0 + tx * 4;
    #pragma unroll
    for (int i = 0; i < 4; i++) {
        int m = M0 + ty * 4 + i;
        float bias; float* dst;
        if (m < 64)       { bias = bq[m];        dst = g_q + (size_t)(b * C8 + m)        * SS; }
        else if (m < 128) { bias = bk[m - 64];   dst = g_k + (size_t)(b * C8 + (m - 64)) * SS; }
        else              { bias = bv[m - 128];  dst = g_v + (size_t)(b * CC + (m - 128))* SS; }
        float4 o;
        o.x = acc[i][0] + bias; o.y = acc[i][1] + bias;
        o.z = acc[i][2] + bias; o.w = acc[i][3] + bias;
        *reinterpret_cast<float4*>(dst + n0) = o;
    }
}

// ---------------- K2: plane transpose (w<->h), 128x128 planes ------------------
__global__ void transpose_wh(float* __restrict__ dst, const float* __restrict__ src) {
    __shared__ float t[32][33];
    const size_t base = (size_t)blockIdx.z * SS;
    const int x0 = blockIdx.x * 32, y0 = blockIdx.y * 32;
    const int tx = threadIdx.x, ty = threadIdx.y; // 32 x 8
    #pragma unroll
    for (int i = 0; i < 32; i += 8)
        t[ty + i][tx] = src[base + (size_t)(y0 + ty + i) * S + x0 + tx];
    __syncthreads();
    #pragma unroll
    for (int i = 0; i < 32; i += 8)
        dst[base + (size_t)(x0 + ty + i) * S + y0 + tx] = t[tx][ty + i];
}

// ---------------- K3: attention logits (col or row) ----------------------------
// col (is_col=1): per (b, p=h): E[w][u] = sum_c qT[b,c,h,w] kT[b,c,h,u], diag mask
// row (is_col=0): per (b, p=w): E[h][u] = sum_c q [b,c,w,h] k [b,c,w,u]
__global__ void attn_logits(const float* __restrict__ qsrc, const float* __restrict__ ksrc,
                            float* __restrict__ att, int is_col) {
    const int p = blockIdx.x;
    const int b = blockIdx.y;
    const int tid = threadIdx.x;
    const int tx = tid & 15, ty = tid >> 4;
    const int r0 = ty * 8, u0 = tx * 8;

    __shared__ float qs[32][128];
    __shared__ float ks[32][128];

    float acc[8][8] = {};
    const size_t qbase = (size_t)b * C8 * SS + (size_t)p * S;

    for (int c0 = 0; c0 < C8; c0 += 32) {
        #pragma unroll
        for (int l = 0; l < 16; l++) {
            int idx = tid + l * 256;       // 0..4095
            int cc = idx >> 7, rr = idx & 127;
            size_t g = qbase + (size_t)(c0 + cc) * SS + rr;
            qs[cc][rr] = qsrc[g];
            ks[cc][rr] = ksrc[g];
        }
        __syncthreads();
        #pragma unroll
        for (int cc = 0; cc < 32; cc++) {
            float qa[8], kb[8];
            #pragma unroll
            for (int i = 0; i < 8; i++) qa[i] = qs[cc][r0 + i];
            #pragma unroll
            for (int j = 0; j < 8; j++) kb[j] = ks[cc][u0 + j];
            #pragma unroll
            for (int i = 0; i < 8; i++)
                #pragma unroll
                for (int j = 0; j < 8; j++)
                    acc[i][j] = fmaf(qa[i], kb[j], acc[i][j]);
        }
        __syncthreads();
    }

    const size_t obase  = (size_t)b * SS * 256 +
                          (is_col ? (size_t)p * 256 : (size_t)p * S * 256 + 128);
    const size_t rstride = is_col ? (size_t)S * 256 : 256;
    #pragma unroll
    for (int i = 0; i < 8; i++) {
        int r = r0 + i;
        #pragma unroll
        for (int j = 0; j < 8; j++) {
            float v = acc[i][j];
            if (is_col && r == u0 + j) v = NEG_INF_F;
            att[obase + (size_t)r * rstride + u0 + j] = v;
        }
    }
}

// ---------------- K4: softmax over 256, one warp per row -----------------------
__global__ void softmax256(float* __restrict__ att) {
    const int row  = blockIdx.x * 8 + (threadIdx.x >> 5);
    const int lane = threadIdx.x & 31;
    float* pr = att + (size_t)row * 256;

    float vals[8];
    float m = -3.4e38f;
    #pragma unroll
    for (int i = 0; i < 8; i++) { vals[i] = pr[lane + i * 32]; m = fmaxf(m, vals[i]); }
    #pragma unroll
    for (int o = 16; o > 0; o >>= 1) m = fmaxf(m, __shfl_xor_sync(0xffffffff, m, o));
    float s = 0.f;
    #pragma unroll
    for (int i = 0; i < 8; i++) { vals[i] = __expf(vals[i] - m); s += vals[i]; }
    #pragma unroll
    for (int o = 16; o > 0; o >>= 1) s += __shfl_xor_sync(0xffffffff, s, o);
    float inv = 1.f / s;
    #pragma unroll
    for (int i = 0; i < 8; i++) pr[lane + i * 32] = vals[i] * inv;
}

// ---------------- K5: attention @ V (col or row) -------------------------------
// col: per (b, p=h), c-tile: O[c][w] = sum_u vT[b,c,h,u] * a_col[b,w,h,u] -> ocolT
// row: per (b, p=w), c-tile: O[c][h] = sum_u v [b,c,w,u] * a_row[b,w,h,u] -> d_out
__global__ void attn_av(const float* __restrict__ vsrc, const float* __restrict__ att,
                        float* __restrict__ dst, int is_col) {
    const int ct = blockIdx.x;        // 0..3 (c tile of 128)
    const int p  = blockIdx.y;        // h (col) or w (row)
    const int b  = blockIdx.z;
    const int tid = threadIdx.x;
    const int tx = tid & 15, ty = tid >> 4;
    const int c0r = ty * 8, q0 = tx * 8;

    __shared__ float Vs[32][129];
    __shared__ float As[32][129];

    float acc[8][8] = {};
    const size_t vbase = (size_t)(b * CC + ct * 128) * SS + (size_t)p * S;
    const size_t abase = (size_t)b * SS * 256 +
                         (is_col ? (size_t)p * 256 : (size_t)p * S * 256 + 128);
    const size_t aq = is_col ? (size_t)S * 256 : 256;

    for (int u0 = 0; u0 < S; u0 += 32) {
        #pragma unroll
        for (int l = 0; l < 16; l++) {
            int idx = tid + l * 256;      // 0..4095, 128 rows x 32 u
            int cp = idx >> 5, up = idx & 31;
            Vs[up][cp] = vsrc[vbase + (size_t)cp * SS + u0 + up];
            As[up][cp] = att [abase + (size_t)cp * aq + u0 + up];
        }
        __syncthreads();
        #pragma unroll
        for (int uu = 0; uu < 32; uu++) {
            float va[8], ab[8];
            #pragma unroll
            for (int i = 0; i < 8; i++) va[i] = Vs[uu][c0r + i];
            #pragma unroll
            for (int j = 0; j < 8; j++) ab[j] = As[uu][q0 + j];
            #pragma unroll
            for (int i = 0; i < 8; i++)
                #pragma unroll
                for (int j = 0; j < 8; j++)
                    acc[i][j] = fmaf(va[i], ab[j], acc[i][j]);
        }
        __syncthreads();
    }

    #pragma unroll
    for (int i = 0; i < 8; i++) {
        size_t o = vbase + (size_t)(c0r + i) * SS + q0;
        #pragma unroll
        for (int j = 0; j < 8; j++) dst[o + j] = acc[i][j];
    }
}

// ---------------- K6: out = gamma * (orow + transpose(ocolT)) + x --------------
__global__ void final_combine(const float* __restrict__ x, const float* __restrict__ gamma,
                              const float* __restrict__ ocolT, float* __restrict__ out) {
    __shared__ float t[32][33];
    const size_t base = (size_t)blockIdx.z * SS;   // plane = b*512 + c
    const int w0 = blockIdx.x * 32, h0 = blockIdx.y * 32;
    const int tx = threadIdx.x, ty = threadIdx.y;  // 32 x 8
    #pragma unroll
    for (int i = 0; i < 32; i += 8)
        t[ty + i][tx] = ocolT[base + (size_t)(h0 + ty + i) * S + w0 + tx];
    __syncthreads();
    const float g = gamma[0];
    #pragma unroll
    for (int i = 0; i < 32; i += 8) {
        size_t o = base + (size_t)(w0 + ty + i) * S + h0 + tx;
        out[o] = g * (out[o] + t[tx][ty + i]) + x[o];
    }
}

// ---------------- launch ------------------------------------------------------
extern "C" void kernel_launch(void* const* d_in, const int* in_sizes, int n_in,
                              void* d_out, int out_size) {
    const float* x     = (const float*)d_in[0];
    const float* Wq    = (const float*)d_in[1];
    const float* bq    = (const float*)d_in[2];
    const float* Wk    = (const float*)d_in[3];
    const float* bk    = (const float*)d_in[4];
    const float* Wv    = (const float*)d_in[5];
    const float* bv    = (const float*)d_in[6];
    const float* gamma = (const float*)d_in[7];
    float* out = (float*)d_out;

    float *q, *k, *qT, *kT, *v, *vT, *att, *ocolT;
    cudaGetSymbolAddress((void**)&q,     g_q);
    cudaGetSymbolAddress((void**)&k,     g_k);
    cudaGetSymbolAddress((void**)&qT,    g_qT);
    cudaGetSymbolAddress((void**)&kT,    g_kT);
    cudaGetSymbolAddress((void**)&v,     g_v);
    cudaGetSymbolAddress((void**)&vT,    g_vT);
    cudaGetSymbolAddress((void**)&att,   g_att);
    cudaGetSymbolAddress((void**)&ocolT, g_ocolT);

    // 1. QKV projection
    qkv_gemm<<<dim3(SS / 64, 640 / 64, BB), 256>>>(x, Wq, bq, Wk, bk, Wv, bv);

    // 2. transposes (w<->h)
    transpose_wh<<<dim3(4, 4, BB * C8), dim3(32, 8)>>>(qT, q);
    transpose_wh<<<dim3(4, 4, BB * C8), dim3(32, 8)>>>(kT, k);
    transpose_wh<<<dim3(4, 4, BB * CC), dim3(32, 8)>>>(vT, v);

    // 3. logits
    attn_logits<<<dim3(S, BB), 256>>>(qT, kT, att, 1);  // col (masked diag)
    attn_logits<<<dim3(S, BB), 256>>>(q,  k,  att, 0);  // row

    // 4. softmax over 256 (col|row concatenated)
    softmax256<<<(BB * SS) / 8, 256>>>(att);

    // 5. attention @ V
    attn_av<<<dim3(4, S, BB), 256>>>(vT, att, ocolT, 1); // col part -> ocolT[b][c][h][w]
    attn_av<<<dim3(4, S, BB), 256>>>(v,  att, out,   0); // row part -> out[b][c][w][h]

    // 6. combine + residual
    final_combine<<<dim3(4, 4, BB * CC), dim3(32, 8)>>>(x, gamma, ocolT, out);
}

// round 3
// speedup vs baseline: 1.8700x; 1.8700x over previous
#include <cuda_runtime.h>
#include <cuda_bf16.h>
#include <cstdint>

#define BB 8
#define CC 512
#define C8 64
#define S  128
#define SS (S*S)
#define NPIX (SS)
#define NEG_INF_F (-1000000000.0f)

// ---------------- scratch buffers (device globals; no allocation) ----------------
__device__ float g_q   [BB * C8 * SS];
__device__ float g_k   [BB * C8 * SS];
__device__ float g_qT  [BB * C8 * SS];
__device__ float g_kT  [BB * C8 * SS];
__device__ float g_v   [BB * CC * SS];
__device__ float g_vT  [BB * CC * SS];
__device__ float g_att [BB * SS * 2 * S];
__device__ float g_ocolT[BB * CC * SS];

// ---------------- mma.sync tf32 helpers ----------------------------------------
__device__ __forceinline__ uint32_t f2tf32(float f) {
    uint32_t u;
    asm("cvt.rn.tf32.f32 %0, %1;" : "=r"(u) : "f"(f));
    return u;
}
__device__ __forceinline__ void mma_tf32(float c[4], const uint32_t a[4], const uint32_t b[2]) {
    asm volatile(
        "mma.sync.aligned.m16n8k8.row.col.f32.tf32.tf32.f32 "
        "{%0,%1,%2,%3}, {%4,%5,%6,%7}, {%8,%9}, {%0,%1,%2,%3};"
        : "+f"(c[0]), "+f"(c[1]), "+f"(c[2]), "+f"(c[3])
        : "r"(a[0]), "r"(a[1]), "r"(a[2]), "r"(a[3]), "r"(b[0]), "r"(b[1]));
}

// ---------------- K1: QKV projection via mma.sync tf32 --------------------------
// D[m=outchan 0..639][n=pixel] = Wcat[m][c] @ x[b][c][n].
// CTA tile 128x128, BK=32. 8 warps: 4 (M) x 2 (N), warp tile 32x64.
// SMEM k-major: As[k][m], Bs[k][n] (tf32 bits), pad 132 to dodge conflicts.
__global__ void __launch_bounds__(256, 2)
qkv_gemm_mma(const float* __restrict__ x,
             const float* __restrict__ Wq, const float* __restrict__ bq,
             const float* __restrict__ Wk, const float* __restrict__ bk,
             const float* __restrict__ Wv, const float* __restrict__ bv) {
    __shared__ uint32_t As[32][132];
    __shared__ uint32_t Bs[32][132];

    const int tid  = threadIdx.x;
    const int lane = tid & 31, wid = tid >> 5;
    const int grp  = lane >> 2, tig = lane & 3;
    const int wm   = (wid >> 1) * 32;   // warp M offset within CTA tile
    const int wn   = (wid & 1) * 64;    // warp N offset
    const int m0   = blockIdx.x * 128;  // 0..512 (5 tiles of 640)
    const int n0   = blockIdx.y * 128;  // pixel tile
    const int b    = blockIdx.z;

    const float* xb = x + (size_t)b * CC * NPIX;

    float acc[2][8][4] = {};

    for (int k0 = 0; k0 < CC; k0 += 32) {
        // ---- load A tile: 128 m x 32 k (transposed store) ----
        #pragma unroll
        for (int l = 0; l < 4; l++) {
            int idx = l * 256 + tid;        // 0..1023 float4 slots
            int m   = idx >> 3;             // 0..127
            int kq  = idx & 7;              // float4 index in k
            int mm  = m0 + m;
            const float* src;
            if (mm < 64)        src = Wq + (size_t)mm * CC;
            else if (mm < 128)  src = Wk + (size_t)(mm - 64) * CC;
            else                src = Wv + (size_t)(mm - 128) * CC;
            float4 v4 = *reinterpret_cast<const float4*>(src + k0 + kq * 4);
            As[kq * 4 + 0][m] = f2tf32(v4.x);
            As[kq * 4 + 1][m] = f2tf32(v4.y);
            As[kq * 4 + 2][m] = f2tf32(v4.z);
            As[kq * 4 + 3][m] = f2tf32(v4.w);
        }
        // ---- load B tile: 32 k x 128 n (direct, n contiguous) ----
        #pragma unroll
        for (int l = 0; l < 4; l++) {
            int idx = l * 256 + tid;        // 0..1023
            int kk  = idx >> 5;             // 0..31
            int nq  = idx & 31;             // float4 index in n
            float4 v4 = *reinterpret_cast<const float4*>(
                xb + (size_t)(k0 + kk) * NPIX + n0 + nq * 4);
            Bs[kk][nq * 4 + 0] = f2tf32(v4.x);
            Bs[kk][nq * 4 + 1] = f2tf32(v4.y);
            Bs[kk][nq * 4 + 2] = f2tf32(v4.z);
            Bs[kk][nq * 4 + 3] = f2tf32(v4.w);
        }
        __syncthreads();

        #pragma unroll
        for (int kk = 0; kk < 4; kk++) {
            const int kr = kk * 8 + tig;
            uint32_t a[2][4], bf[8][2];
            #pragma unroll
            for (int i = 0; i < 2; i++) {
                a[i][0] = As[kr    ][wm + i * 16 + grp];
                a[i][1] = As[kr    ][wm + i * 16 + grp + 8];
                a[i][2] = As[kr + 4][wm + i * 16 + grp];
                a[i][3] = As[kr + 4][wm + i * 16 + grp + 8];
            }
            #pragma unroll
            for (int j = 0; j < 8; j++) {
                bf[j][0] = Bs[kr    ][wn + j * 8 + grp];
                bf[j][1] = Bs[kr + 4][wn + j * 8 + grp];
            }
            #pragma unroll
            for (int i = 0; i < 2; i++)
                #pragma unroll
                for (int j = 0; j < 8; j++)
                    mma_tf32(acc[i][j], a[i], bf[j]);
        }
        __syncthreads();
    }

    // ---- epilogue: bias + route rows to g_q / g_k / g_v ----
    #pragma unroll
    for (int i = 0; i < 2; i++) {
        #pragma unroll
        for (int r = 0; r < 2; r++) {       // r=0 -> c0/c1 (row grp), r=1 -> c2/c3 (row grp+8)
            int m = m0 + wm + i * 16 + grp + r * 8;
            float bias; float* dst;
            if (m < 64)        { bias = bq[m];        dst = g_q + ((size_t)b * C8 + m) * SS; }
            else if (m < 128)  { bias = bk[m - 64];   dst = g_k + ((size_t)b * C8 + m - 64) * SS; }
            else               { bias = bv[m - 128];  dst = g_v + ((size_t)b * CC + m - 128) * SS; }
            float* row = dst + n0 + wn + tig * 2;
            #pragma unroll
            for (int j = 0; j < 8; j++) {
                float2 o;
                o.x = acc[i][j][r * 2 + 0] + bias;
                o.y = acc[i][j][r * 2 + 1] + bias;
                *reinterpret_cast<float2*>(row + j * 8) = o;
            }
        }
    }
}

// ---------------- K2: plane transpose (w<->h), 128x128 planes ------------------
__global__ void transpose_wh(float* __restrict__ dst, const float* __restrict__ src) {
    __shared__ float t[32][33];
    const size_t base = (size_t)blockIdx.z * SS;
    const int x0 = blockIdx.x * 32, y0 = blockIdx.y * 32;
    const int tx = threadIdx.x, ty = threadIdx.y;
    #pragma unroll
    for (int i = 0; i < 32; i += 8)
        t[ty + i][tx] = src[base + (size_t)(y0 + ty + i) * S + x0 + tx];
    __syncthreads();
    #pragma unroll
    for (int i = 0; i < 32; i += 8)
        dst[base + (size_t)(x0 + ty + i) * S + y0 + tx] = t[tx][ty + i];
}

// ---------------- K3: attention logits (col or row) ----------------------------
__global__ void attn_logits(const float* __restrict__ qsrc, const float* __restrict__ ksrc,
                            float* __restrict__ att, int is_col) {
    const int p = blockIdx.x;
    const int b = blockIdx.y;
    const int tid = threadIdx.x;
    const int tx = tid & 15, ty = tid >> 4;
    const int r0 = ty * 8, u0 = tx * 8;

    __shared__ float qs[32][128];
    __shared__ float ks[32][128];

    float acc[8][8] = {};
    const size_t qbase = (size_t)b * C8 * SS + (size_t)p * S;

    for (int c0 = 0; c0 < C8; c0 += 32) {
        #pragma unroll
        for (int l = 0; l < 16; l++) {
            int idx = tid + l * 256;
            int cc = idx >> 7, rr = idx & 127;
            size_t g = qbase + (size_t)(c0 + cc) * SS + rr;
            qs[cc][rr] = qsrc[g];
            ks[cc][rr] = ksrc[g];
        }
        __syncthreads();
        #pragma unroll
        for (int cc = 0; cc < 32; cc++) {
            float qa[8], kb[8];
            #pragma unroll
            for (int i = 0; i < 8; i++) qa[i] = qs[cc][r0 + i];
            #pragma unroll
            for (int j = 0; j < 8; j++) kb[j] = ks[cc][u0 + j];
            #pragma unroll
            for (int i = 0; i < 8; i++)
                #pragma unroll
                for (int j = 0; j < 8; j++)
                    acc[i][j] = fmaf(qa[i], kb[j], acc[i][j]);
        }
        __syncthreads();
    }

    const size_t obase  = (size_t)b * SS * 256 +
                          (is_col ? (size_t)p * 256 : (size_t)p * S * 256 + 128);
    const size_t rstride = is_col ? (size_t)S * 256 : 256;
    #pragma unroll
    for (int i = 0; i < 8; i++) {
        int r = r0 + i;
        #pragma unroll
        for (int j = 0; j < 8; j++) {
            float v = acc[i][j];
            if (is_col && r == u0 + j) v = NEG_INF_F;
            att[obase + (size_t)r * rstride + u0 + j] = v;
        }
    }
}

// ---------------- K4: softmax over 256, one warp per row -----------------------
__global__ void softmax256(float* __restrict__ att) {
    const int row  = blockIdx.x * 8 + (threadIdx.x >> 5);
    const int lane = threadIdx.x & 31;
    float* pr = att + (size_t)row * 256;

    float vals[8];
    float m = -3.4e38f;
    #pragma unroll
    for (int i = 0; i < 8; i++) { vals[i] = pr[lane + i * 32]; m = fmaxf(m, vals[i]); }
    #pragma unroll
    for (int o = 16; o > 0; o >>= 1) m = fmaxf(m, __shfl_xor_sync(0xffffffff, m, o));
    float s = 0.f;
    #pragma unroll
    for (int i = 0; i < 8; i++) { vals[i] = __expf(vals[i] - m); s += vals[i]; }
    #pragma unroll
    for (int o = 16; o > 0; o >>= 1) s += __shfl_xor_sync(0xffffffff, s, o);
    float inv = 1.f / s;
    #pragma unroll
    for (int i = 0; i < 8; i++) pr[lane + i * 32] = vals[i] * inv;
}

// ---------------- K5: attention @ V (col or row) -------------------------------
__global__ void attn_av(const float* __restrict__ vsrc, const float* __restrict__ att,
                        float* __restrict__ dst, int is_col) {
    const int ct = blockIdx.x;
    const int p  = blockIdx.y;
    const int b  = blockIdx.z;
    const int tid = threadIdx.x;
    const int tx = tid & 15, ty = tid >> 4;
    const int c0r = ty * 8, q0 = tx * 8;

    __shared__ float Vs[32][129];
    __shared__ float As[32][129];

    float acc[8][8] = {};
    const size_t vbase = (size_t)(b * CC + ct * 128) * SS + (size_t)p * S;
    const size_t abase = (size_t)b * SS * 256 +
                         (is_col ? (size_t)p * 256 : (size_t)p * S * 256 + 128);
    const size_t aq = is_col ? (size_t)S * 256 : 256;

    for (int u0 = 0; u0 < S; u0 += 32) {
        #pragma unroll
        for (int l = 0; l < 16; l++) {
            int idx = tid + l * 256;
            int cp = idx >> 5, up = idx & 31;
            Vs[up][cp] = vsrc[vbase + (size_t)cp * SS + u0 + up];
            As[up][cp] = att [abase + (size_t)cp * aq + u0 + up];
        }
        __syncthreads();
        #pragma unroll
        for (int uu = 0; uu < 32; uu++) {
            float va[8], ab[8];
            #pragma unroll
            for (int i = 0; i < 8; i++) va[i] = Vs[uu][c0r + i];
            #pragma unroll
            for (int j = 0; j < 8; j++) ab[j] = As[uu][q0 + j];
            #pragma unroll
            for (int i = 0; i < 8; i++)
                #pragma unroll
                for (int j = 0; j < 8; j++)
                    acc[i][j] = fmaf(va[i], ab[j], acc[i][j]);
        }
        __syncthreads();
    }

    #pragma unroll
    for (int i = 0; i < 8; i++) {
        size_t o = vbase + (size_t)(c0r + i) * SS + q0;
        #pragma unroll
        for (int j = 0; j < 8; j++) dst[o + j] = acc[i][j];
    }
}

// ---------------- K6: out = gamma * (orow + transpose(ocolT)) + x --------------
__global__ void final_combine(const float* __restrict__ x, const float* __restrict__ gamma,
                              const float* __restrict__ ocolT, float* __restrict__ out) {
    __shared__ float t[32][33];
    const size_t base = (size_t)blockIdx.z * SS;
    const int w0 = blockIdx.x * 32, h0 = blockIdx.y * 32;
    const int tx = threadIdx.x, ty = threadIdx.y;
    #pragma unroll
    for (int i = 0; i < 32; i += 8)
        t[ty + i][tx] = ocolT[base + (size_t)(h0 + ty + i) * S + w0 + tx];
    __syncthreads();
    const float g = gamma[0];
    #pragma unroll
    for (int i = 0; i < 32; i += 8) {
        size_t o = base + (size_t)(w0 + ty + i) * S + h0 + tx;
        out[o] = g * (out[o] + t[tx][ty + i]) + x[o];
    }
}

// ---------------- launch ------------------------------------------------------
extern "C" void kernel_launch(void* const* d_in, const int* in_sizes, int n_in,
                              void* d_out, int out_size) {
    const float* x     = (const float*)d_in[0];
    const float* Wq    = (const float*)d_in[1];
    const float* bq    = (const float*)d_in[2];
    const float* Wk    = (const float*)d_in[3];
    const float* bk    = (const float*)d_in[4];
    const float* Wv    = (const float*)d_in[5];
    const float* bv    = (const float*)d_in[6];
    const float* gamma = (const float*)d_in[7];
    float* out = (float*)d_out;

    float *q, *k, *qT, *kT, *v, *vT, *att, *ocolT;
    cudaGetSymbolAddress((void**)&q,     g_q);
    cudaGetSymbolAddress((void**)&k,     g_k);
    cudaGetSymbolAddress((void**)&qT,    g_qT);
    cudaGetSymbolAddress((void**)&kT,    g_kT);
    cudaGetSymbolAddress((void**)&v,     g_v);
    cudaGetSymbolAddress((void**)&vT,    g_vT);
    cudaGetSymbolAddress((void**)&att,   g_att);
    cudaGetSymbolAddress((void**)&ocolT, g_ocolT);

    // 1. QKV projection on tensor cores (mma.sync tf32)
    qkv_gemm_mma<<<dim3(5, NPIX / 128, BB), 256>>>(x, Wq, bq, Wk, bk, Wv, bv);

    // 2. transposes (w<->h)
    transpose_wh<<<dim3(4, 4, BB * C8), dim3(32, 8)>>>(qT, q);
    transpose_wh<<<dim3(4, 4, BB * C8), dim3(32, 8)>>>(kT, k);
    transpose_wh<<<dim3(4, 4, BB * CC), dim3(32, 8)>>>(vT, v);

    // 3. logits
    attn_logits<<<dim3(S, BB), 256>>>(qT, kT, att, 1);
    attn_logits<<<dim3(S, BB), 256>>>(q,  k,  att, 0);

    // 4. softmax
    softmax256<<<(BB * SS) / 8, 256>>>(att);

    // 5. attention @ V
    attn_av<<<dim3(4, S, BB), 256>>>(vT, att, ocolT, 1);
    attn_av<<<dim3(4, S, BB), 256>>>(v,  att, out,   0);

    // 6. combine + residual
    final_combine<<<dim3(4, 4, BB * CC), dim3(32, 8)>>>(x, gamma, ocolT, out);
}

// round 4
// speedup vs baseline: 3.5690x; 1.9085x over previous
#include <cuda_runtime.h>
#include <cuda_bf16.h>
#include <cstdint>

#define BB 8
#define CC 512
#define C8 64
#define S  128
#define SS (S*S)
#define NPIX (SS)
#define NEG_INF_F (-1000000000.0f)

// ---------------- scratch buffers (device globals; no allocation) ----------------
__device__ float g_q   [BB * C8 * SS];
__device__ float g_k   [BB * C8 * SS];
__device__ float g_qT  [BB * C8 * SS];
__device__ float g_kT  [BB * C8 * SS];
__device__ float g_v   [BB * CC * SS];
__device__ float g_vT  [BB * CC * SS];
__device__ float g_att [BB * SS * 2 * S];
__device__ float g_ocolT[BB * CC * SS];

// ---------------- mma.sync tf32 helpers ----------------------------------------
__device__ __forceinline__ uint32_t f2tf32(float f) {
    uint32_t u;
    asm("cvt.rn.tf32.f32 %0, %1;" : "=r"(u) : "f"(f));
    return u;
}
__device__ __forceinline__ void mma_tf32(float c[4], const uint32_t a[4], const uint32_t b[2]) {
    asm volatile(
        "mma.sync.aligned.m16n8k8.row.col.f32.tf32.tf32.f32 "
        "{%0,%1,%2,%3}, {%4,%5,%6,%7}, {%8,%9}, {%0,%1,%2,%3};"
        : "+f"(c[0]), "+f"(c[1]), "+f"(c[2]), "+f"(c[3])
        : "r"(a[0]), "r"(a[1]), "r"(a[2]), "r"(a[3]), "r"(b[0]), "r"(b[1]));
}

// ---------------- K1: QKV projection via mma.sync tf32 --------------------------
__global__ void __launch_bounds__(256, 2)
qkv_gemm_mma(const float* __restrict__ x,
             const float* __restrict__ Wq, const float* __restrict__ bq,
             const float* __restrict__ Wk, const float* __restrict__ bk,
             const float* __restrict__ Wv, const float* __restrict__ bv) {
    __shared__ uint32_t As[32][132];
    __shared__ uint32_t Bs[32][132];

    const int tid  = threadIdx.x;
    const int lane = tid & 31, wid = tid >> 5;
    const int grp  = lane >> 2, tig = lane & 3;
    const int wm   = (wid >> 1) * 32;
    const int wn   = (wid & 1) * 64;
    const int m0   = blockIdx.x * 128;
    const int n0   = blockIdx.y * 128;
    const int b    = blockIdx.z;

    const float* xb = x + (size_t)b * CC * NPIX;

    float acc[2][8][4] = {};

    for (int k0 = 0; k0 < CC; k0 += 32) {
        #pragma unroll
        for (int l = 0; l < 4; l++) {
            int idx = l * 256 + tid;
            int m   = idx >> 3;
            int kq  = idx & 7;
            int mm  = m0 + m;
            const float* src;
            if (mm < 64)        src = Wq + (size_t)mm * CC;
            else if (mm < 128)  src = Wk + (size_t)(mm - 64) * CC;
            else                src = Wv + (size_t)(mm - 128) * CC;
            float4 v4 = *reinterpret_cast<const float4*>(src + k0 + kq * 4);
            As[kq * 4 + 0][m] = f2tf32(v4.x);
            As[kq * 4 + 1][m] = f2tf32(v4.y);
            As[kq * 4 + 2][m] = f2tf32(v4.z);
            As[kq * 4 + 3][m] = f2tf32(v4.w);
        }
        #pragma unroll
        for (int l = 0; l < 4; l++) {
            int idx = l * 256 + tid;
            int kk  = idx >> 5;
            int nq  = idx & 31;
            float4 v4 = *reinterpret_cast<const float4*>(
                xb + (size_t)(k0 + kk) * NPIX + n0 + nq * 4);
            Bs[kk][nq * 4 + 0] = f2tf32(v4.x);
            Bs[kk][nq * 4 + 1] = f2tf32(v4.y);
            Bs[kk][nq * 4 + 2] = f2tf32(v4.z);
            Bs[kk][nq * 4 + 3] = f2tf32(v4.w);
        }
        __syncthreads();

        #pragma unroll
        for (int kk = 0; kk < 4; kk++) {
            const int kr = kk * 8 + tig;
            uint32_t a[2][4], bf[8][2];
            #pragma unroll
            for (int i = 0; i < 2; i++) {
                a[i][0] = As[kr    ][wm + i * 16 + grp];
                a[i][1] = As[kr    ][wm + i * 16 + grp + 8];
                a[i][2] = As[kr + 4][wm + i * 16 + grp];
                a[i][3] = As[kr + 4][wm + i * 16 + grp + 8];
            }
            #pragma unroll
            for (int j = 0; j < 8; j++) {
                bf[j][0] = Bs[kr    ][wn + j * 8 + grp];
                bf[j][1] = Bs[kr + 4][wn + j * 8 + grp];
            }
            #pragma unroll
            for (int i = 0; i < 2; i++)
                #pragma unroll
                for (int j = 0; j < 8; j++)
                    mma_tf32(acc[i][j], a[i], bf[j]);
        }
        __syncthreads();
    }

    #pragma unroll
    for (int i = 0; i < 2; i++) {
        #pragma unroll
        for (int r = 0; r < 2; r++) {
            int m = m0 + wm + i * 16 + grp + r * 8;
            float bias; float* dst;
            if (m < 64)        { bias = bq[m];        dst = g_q + ((size_t)b * C8 + m) * SS; }
            else if (m < 128)  { bias = bk[m - 64];   dst = g_k + ((size_t)b * C8 + m - 64) * SS; }
            else               { bias = bv[m - 128];  dst = g_v + ((size_t)b * CC + m - 128) * SS; }
            float* row = dst + n0 + wn + tig * 2;
            #pragma unroll
            for (int j = 0; j < 8; j++) {
                float2 o;
                o.x = acc[i][j][r * 2 + 0] + bias;
                o.y = acc[i][j][r * 2 + 1] + bias;
                *reinterpret_cast<float2*>(row + j * 8) = o;
            }
        }
    }
}

// ---------------- K2: plane transpose (w<->h), 128x128 planes ------------------
__global__ void transpose_wh(float* __restrict__ dst, const float* __restrict__ src) {
    __shared__ float t[32][33];
    const size_t base = (size_t)blockIdx.z * SS;
    const int x0 = blockIdx.x * 32, y0 = blockIdx.y * 32;
    const int tx = threadIdx.x, ty = threadIdx.y;
    #pragma unroll
    for (int i = 0; i < 32; i += 8)
        t[ty + i][tx] = src[base + (size_t)(y0 + ty + i) * S + x0 + tx];
    __syncthreads();
    #pragma unroll
    for (int i = 0; i < 32; i += 8)
        dst[base + (size_t)(x0 + ty + i) * S + y0 + tx] = t[tx][ty + i];
}

// ---------------- K3: attention logits via mma.sync tf32 -----------------------
// Per CTA (p, b): E[r=0..127][u=0..127] = sum_c Q[c][r] * K[c][u]   (K=64)
// col (is_col=1): Q=qT,K=kT at plane offset p*S (r=w,u=w'), mask diag, rstride=S*256
// row (is_col=0): Q=q, K=k  at plane offset p*S (r=h,u=h'), rstride=256, +128 col off
__global__ void __launch_bounds__(256, 2)
attn_logits_mma(const float* __restrict__ qsrc, const float* __restrict__ ksrc,
                float* __restrict__ att, int is_col) {
    __shared__ uint32_t Qs[32][132];
    __shared__ uint32_t Ks[32][132];

    const int p = blockIdx.x;
    const int b = blockIdx.y;
    const int tid  = threadIdx.x;
    const int lane = tid & 31, wid = tid >> 5;
    const int grp  = lane >> 2, tig = lane & 3;
    const int wm   = (wid >> 1) * 32;
    const int wn   = (wid & 1) * 64;

    const size_t qbase = (size_t)b * C8 * SS + (size_t)p * S;

    float acc[2][8][4] = {};

    for (int c0 = 0; c0 < C8; c0 += 32) {
        // both tiles are [c][pixel] with pixel contiguous -> direct stores
        #pragma unroll
        for (int l = 0; l < 4; l++) {
            int idx = l * 256 + tid;     // 1024 float4 slots: 32 c x 32 q4
            int cc  = idx >> 5;
            int nq  = idx & 31;
            size_t g = qbase + (size_t)(c0 + cc) * SS + nq * 4;
            float4 vq = *reinterpret_cast<const float4*>(qsrc + g);
            float4 vk = *reinterpret_cast<const float4*>(ksrc + g);
            Qs[cc][nq * 4 + 0] = f2tf32(vq.x);
            Qs[cc][nq * 4 + 1] = f2tf32(vq.y);
            Qs[cc][nq * 4 + 2] = f2tf32(vq.z);
            Qs[cc][nq * 4 + 3] = f2tf32(vq.w);
            Ks[cc][nq * 4 + 0] = f2tf32(vk.x);
            Ks[cc][nq * 4 + 1] = f2tf32(vk.y);
            Ks[cc][nq * 4 + 2] = f2tf32(vk.z);
            Ks[cc][nq * 4 + 3] = f2tf32(vk.w);
        }
        __syncthreads();

        #pragma unroll
        for (int kk = 0; kk < 4; kk++) {
            const int kr = kk * 8 + tig;
            uint32_t a[2][4], bf[8][2];
            #pragma unroll
            for (int i = 0; i < 2; i++) {
                a[i][0] = Qs[kr    ][wm + i * 16 + grp];
                a[i][1] = Qs[kr    ][wm + i * 16 + grp + 8];
                a[i][2] = Qs[kr + 4][wm + i * 16 + grp];
                a[i][3] = Qs[kr + 4][wm + i * 16 + grp + 8];
            }
            #pragma unroll
            for (int j = 0; j < 8; j++) {
                bf[j][0] = Ks[kr    ][wn + j * 8 + grp];
                bf[j][1] = Ks[kr + 4][wn + j * 8 + grp];
            }
            #pragma unroll
            for (int i = 0; i < 2; i++)
                #pragma unroll
                for (int j = 0; j < 8; j++)
                    mma_tf32(acc[i][j], a[i], bf[j]);
        }
        __syncthreads();
    }

    const size_t obase  = (size_t)b * SS * 256 +
                          (is_col ? (size_t)p * 256 : (size_t)p * S * 256 + 128);
    const size_t rstride = is_col ? (size_t)S * 256 : 256;
    #pragma unroll
    for (int i = 0; i < 2; i++) {
        #pragma unroll
        for (int r = 0; r < 2; r++) {
            int rr = wm + i * 16 + grp + r * 8;
            float* row = att + obase + (size_t)rr * rstride + wn + tig * 2;
            #pragma unroll
            for (int j = 0; j < 8; j++) {
                int u = wn + j * 8 + tig * 2;
                float2 o;
                o.x = (is_col && rr == u)     ? NEG_INF_F : acc[i][j][r * 2 + 0];
                o.y = (is_col && rr == u + 1) ? NEG_INF_F : acc[i][j][r * 2 + 1];
                *reinterpret_cast<float2*>(row + j * 8) = o;
            }
        }
    }
}

// ---------------- K4: softmax over 256, one warp per row -----------------------
__global__ void softmax256(float* __restrict__ att) {
    const int row  = blockIdx.x * 8 + (threadIdx.x >> 5);
    const int lane = threadIdx.x & 31;
    float* pr = att + (size_t)row * 256;

    float vals[8];
    float m = -3.4e38f;
    #pragma unroll
    for (int i = 0; i < 8; i++) { vals[i] = pr[lane + i * 32]; m = fmaxf(m, vals[i]); }
    #pragma unroll
    for (int o = 16; o > 0; o >>= 1) m = fmaxf(m, __shfl_xor_sync(0xffffffff, m, o));
    float s = 0.f;
    #pragma unroll
    for (int i = 0; i < 8; i++) { vals[i] = __expf(vals[i] - m); s += vals[i]; }
    #pragma unroll
    for (int o = 16; o > 0; o >>= 1) s += __shfl_xor_sync(0xffffffff, s, o);
    float inv = 1.f / s;
    #pragma unroll
    for (int i = 0; i < 8; i++) pr[lane + i * 32] = vals[i] * inv;
}

// ---------------- K5: attention @ V via mma.sync tf32 --------------------------
// Per CTA (ct, p, b): O[c=0..127][q=0..127] = sum_u V[c][u] * Att[q][u]  (K=128)
__global__ void __launch_bounds__(256, 2)
attn_av_mma(const float* __restrict__ vsrc, const float* __restrict__ att,
            float* __restrict__ dst, int is_col) {
    __shared__ uint32_t Vs[32][132];   // [u][c]
    __shared__ uint32_t Ts[32][132];   // [u][q]

    const int ct = blockIdx.x;
    const int p  = blockIdx.y;
    const int b  = blockIdx.z;
    const int tid  = threadIdx.x;
    const int lane = tid & 31, wid = tid >> 5;
    const int grp  = lane >> 4 == 0 ? (lane >> 2) : (lane >> 2);  // lane>>2
    const int g8   = lane >> 2, tig = lane & 3;
    const int wm   = (wid >> 1) * 32;
    const int wn   = (wid & 1) * 64;

    const size_t vbase = (size_t)(b * CC + ct * 128) * SS + (size_t)p * S;
    const size_t abase = (size_t)b * SS * 256 +
                         (is_col ? (size_t)p * 256 : (size_t)p * S * 256 + 128);
    const size_t aq = is_col ? (size_t)S * 256 : 256;

    float acc[2][8][4] = {};

    for (int u0 = 0; u0 < S; u0 += 32) {
        // V tile: rows c (stride SS), 32 u contiguous -> transposed store [u][c]
        #pragma unroll
        for (int l = 0; l < 4; l++) {
            int idx = l * 256 + tid;    // 1024 slots: 128 c x 8 uq
            int cp  = idx >> 3;
            int uq  = idx & 7;
            float4 v4 = *reinterpret_cast<const float4*>(
                vsrc + vbase + (size_t)cp * SS + u0 + uq * 4);
            Vs[uq * 4 + 0][cp] = f2tf32(v4.x);
            Vs[uq * 4 + 1][cp] = f2tf32(v4.y);
            Vs[uq * 4 + 2][cp] = f2tf32(v4.z);
            Vs[uq * 4 + 3][cp] = f2tf32(v4.w);
        }
        // Att tile: rows q (stride aq), 32 u contiguous -> transposed store [u][q]
        #pragma unroll
        for (int l = 0; l < 4; l++) {
            int idx = l * 256 + tid;
            int qp  = idx >> 3;
            int uq  = idx & 7;
            float4 v4 = *reinterpret_cast<const float4*>(
                att + abase + (size_t)qp * aq + u0 + uq * 4);
            Ts[uq * 4 + 0][qp] = f2tf32(v4.x);
            Ts[uq * 4 + 1][qp] = f2tf32(v4.y);
            Ts[uq * 4 + 2][qp] = f2tf32(v4.z);
            Ts[uq * 4 + 3][qp] = f2tf32(v4.w);
        }
        __syncthreads();

        #pragma unroll
        for (int kk = 0; kk < 4; kk++) {
            const int kr = kk * 8 + tig;
            uint32_t a[2][4], bf[8][2];
            #pragma unroll
            for (int i = 0; i < 2; i++) {
                a[i][0] = Vs[kr    ][wm + i * 16 + g8];
                a[i][1] = Vs[kr    ][wm + i * 16 + g8 + 8];
                a[i][2] = Vs[kr + 4][wm + i * 16 + g8];
                a[i][3] = Vs[kr + 4][wm + i * 16 + g8 + 8];
            }
            #pragma unroll
            for (int j = 0; j < 8; j++) {
                bf[j][0] = Ts[kr    ][wn + j * 8 + g8];
                bf[j][1] = Ts[kr + 4][wn + j * 8 + g8];
            }
            #pragma unroll
            for (int i = 0; i < 2; i++)
                #pragma unroll
                for (int j = 0; j < 8; j++)
                    mma_tf32(acc[i][j], a[i], bf[j]);
        }
        __syncthreads();
    }

    // epilogue: O[c][q] -> dst + vbase + c*SS + q
    #pragma unroll
    for (int i = 0; i < 2; i++) {
        #pragma unroll
        for (int r = 0; r < 2; r++) {
            int cl = wm + i * 16 + g8 + r * 8;
            float* row = dst + vbase + (size_t)cl * SS + wn + tig * 2;
            #pragma unroll
            for (int j = 0; j < 8; j++) {
                float2 o;
                o.x = acc[i][j][r * 2 + 0];
                o.y = acc[i][j][r * 2 + 1];
                *reinterpret_cast<float2*>(row + j * 8) = o;
            }
        }
    }
}

// ---------------- K6: out = gamma * (orow + transpose(ocolT)) + x --------------
__global__ void final_combine(const float* __restrict__ x, const float* __restrict__ gamma,
                              const float* __restrict__ ocolT, float* __restrict__ out) {
    __shared__ float t[32][33];
    const size_t base = (size_t)blockIdx.z * SS;
    const int w0 = blockIdx.x * 32, h0 = blockIdx.y * 32;
    const int tx = threadIdx.x, ty = threadIdx.y;
    #pragma unroll
    for (int i = 0; i < 32; i += 8)
        t[ty + i][tx] = ocolT[base + (size_t)(h0 + ty + i) * S + w0 + tx];
    __syncthreads();
    const float g = gamma[0];
    #pragma unroll
    for (int i = 0; i < 32; i += 8) {
        size_t o = base + (size_t)(w0 + ty + i) * S + h0 + tx;
        out[o] = g * (out[o] + t[tx][ty + i]) + x[o];
    }
}

// ---------------- launch ------------------------------------------------------
extern "C" void kernel_launch(void* const* d_in, const int* in_sizes, int n_in,
                              void* d_out, int out_size) {
    const float* x     = (const float*)d_in[0];
    const float* Wq    = (const float*)d_in[1];
    const float* bq    = (const float*)d_in[2];
    const float* Wk    = (const float*)d_in[3];
    const float* bk    = (const float*)d_in[4];
    const float* Wv    = (const float*)d_in[5];
    const float* bv    = (const float*)d_in[6];
    const float* gamma = (const float*)d_in[7];
    float* out = (float*)d_out;

    float *q, *k, *qT, *kT, *v, *vT, *att, *ocolT;
    cudaGetSymbolAddress((void**)&q,     g_q);
    cudaGetSymbolAddress((void**)&k,     g_k);
    cudaGetSymbolAddress((void**)&qT,    g_qT);
    cudaGetSymbolAddress((void**)&kT,    g_kT);
    cudaGetSymbolAddress((void**)&v,     g_v);
    cudaGetSymbolAddress((void**)&vT,    g_vT);
    cudaGetSymbolAddress((void**)&att,   g_att);
    cudaGetSymbolAddress((void**)&ocolT, g_ocolT);

    // 1. QKV projection (tensor cores, tf32)
    qkv_gemm_mma<<<dim3(5, NPIX / 128, BB), 256>>>(x, Wq, bq, Wk, bk, Wv, bv);

    // 2. transposes (w<->h)
    transpose_wh<<<dim3(4, 4, BB * C8), dim3(32, 8)>>>(qT, q);
    transpose_wh<<<dim3(4, 4, BB * C8), dim3(32, 8)>>>(kT, k);
    transpose_wh<<<dim3(4, 4, BB * CC), dim3(32, 8)>>>(vT, v);

    // 3. logits (tensor cores)
    attn_logits_mma<<<dim3(S, BB), 256>>>(qT, kT, att, 1);
    attn_logits_mma<<<dim3(S, BB), 256>>>(q,  k,  att, 0);

    // 4. softmax
    softmax256<<<(BB * SS) / 8, 256>>>(att);

    // 5. attention @ V (tensor cores)
    attn_av_mma<<<dim3(4, S, BB), 256>>>(vT, att, ocolT, 1);
    attn_av_mma<<<dim3(4, S, BB), 256>>>(v,  att, out,   0);

    // 6. combine + residual
    final_combine<<<dim3(4, 4, BB * CC), dim3(32, 8)>>>(x, gamma, ocolT, out);
}

// round 5
// speedup vs baseline: 3.6127x; 1.0122x over previous
#include <cuda_runtime.h>
#include <cuda_bf16.h>
#include <cstdint>

#define BB 8
#define CC 512
#define C8 64
#define S  128
#define SS (S*S)
#define NPIX (SS)
#define NEG_INF_F (-1000000000.0f)

// ---------------- scratch buffers (device globals; no allocation) ----------------
__device__ float g_q   [BB * C8 * SS];
__device__ float g_k   [BB * C8 * SS];
__device__ float g_qT  [BB * C8 * SS];
__device__ float g_kT  [BB * C8 * SS];
__device__ float g_v   [BB * CC * SS];
__device__ float g_vT  [BB * CC * SS];
__device__ float g_att [BB * SS * 2 * S];
__device__ float g_ocolT[BB * CC * SS];

// ---------------- mma.sync tf32 helpers ----------------------------------------
__device__ __forceinline__ uint32_t f2tf32(float f) {
    uint32_t u;
    asm("cvt.rn.tf32.f32 %0, %1;" : "=r"(u) : "f"(f));
    return u;
}
__device__ __forceinline__ void mma_tf32(float c[4], const uint32_t a[4], const uint32_t b[2]) {
    asm volatile(
        "mma.sync.aligned.m16n8k8.row.col.f32.tf32.tf32.f32 "
        "{%0,%1,%2,%3}, {%4,%5,%6,%7}, {%8,%9}, {%0,%1,%2,%3};"
        : "+f"(c[0]), "+f"(c[1]), "+f"(c[2]), "+f"(c[3])
        : "r"(a[0]), "r"(a[1]), "r"(a[2]), "r"(a[3]), "r"(b[0]), "r"(b[1]));
}

#define TILE32 (32 * 132)   // one 32-row tile (132-col padded), in uint32 elems

// ---------------- K1: QKV projection, pipelined double-buffered -----------------
__global__ void __launch_bounds__(256, 2)
qkv_gemm_mma(const float* __restrict__ x,
             const float* __restrict__ Wq, const float* __restrict__ bq,
             const float* __restrict__ Wk, const float* __restrict__ bk,
             const float* __restrict__ Wv, const float* __restrict__ bv) {
    extern __shared__ uint32_t sm[];   // [A0|B0|A1|B1], each TILE32

    const int tid  = threadIdx.x;
    const int lane = tid & 31, wid = tid >> 5;
    const int grp  = lane >> 2, tig = lane & 3;
    const int wm   = (wid >> 1) * 32;
    const int wn   = (wid & 1) * 64;
    const int m0   = blockIdx.x * 128;
    const int n0   = blockIdx.y * 128;
    const int b    = blockIdx.z;

    const float* xb = x + (size_t)b * CC * NPIX;

    float acc[2][8][4] = {};
    float4 pa[4], pb[4];

    auto ldg_tile = [&](int k0) {
        #pragma unroll
        for (int l = 0; l < 4; l++) {
            int idx = l * 256 + tid;
            int m = idx >> 3, kq = idx & 7;
            int mm = m0 + m;
            const float* src;
            if (mm < 64)        src = Wq + (size_t)mm * CC;
            else if (mm < 128)  src = Wk + (size_t)(mm - 64) * CC;
            else                src = Wv + (size_t)(mm - 128) * CC;
            pa[l] = *reinterpret_cast<const float4*>(src + k0 + kq * 4);
        }
        #pragma unroll
        for (int l = 0; l < 4; l++) {
            int idx = l * 256 + tid;
            int kk = idx >> 5, nq = idx & 31;
            pb[l] = *reinterpret_cast<const float4*>(
                xb + (size_t)(k0 + kk) * NPIX + n0 + nq * 4);
        }
    };
    auto sts_tile = [&](int buf) {
        uint32_t* A = sm + buf * 2 * TILE32;
        uint32_t* B = A + TILE32;
        #pragma unroll
        for (int l = 0; l < 4; l++) {
            int idx = l * 256 + tid;
            int m = idx >> 3, kq = idx & 7;
            A[(kq * 4 + 0) * 132 + m] = f2tf32(pa[l].x);
            A[(kq * 4 + 1) * 132 + m] = f2tf32(pa[l].y);
            A[(kq * 4 + 2) * 132 + m] = f2tf32(pa[l].z);
            A[(kq * 4 + 3) * 132 + m] = f2tf32(pa[l].w);
        }
        #pragma unroll
        for (int l = 0; l < 4; l++) {
            int idx = l * 256 + tid;
            int kk = idx >> 5, nq = idx & 31;
            B[kk * 132 + nq * 4 + 0] = f2tf32(pb[l].x);
            B[kk * 132 + nq * 4 + 1] = f2tf32(pb[l].y);
            B[kk * 132 + nq * 4 + 2] = f2tf32(pb[l].z);
            B[kk * 132 + nq * 4 + 3] = f2tf32(pb[l].w);
        }
    };

    ldg_tile(0);
    sts_tile(0);
    __syncthreads();

    for (int i = 0; i < 16; i++) {
        if (i < 15) ldg_tile((i + 1) * 32);

        const uint32_t* A = sm + (i & 1) * 2 * TILE32;
        const uint32_t* B = A + TILE32;
        #pragma unroll
        for (int kk = 0; kk < 4; kk++) {
            const int kr = kk * 8 + tig;
            uint32_t a[2][4], bf[8][2];
            #pragma unroll
            for (int ii = 0; ii < 2; ii++) {
                a[ii][0] = A[kr * 132       + wm + ii * 16 + grp];
                a[ii][1] = A[kr * 132       + wm + ii * 16 + grp + 8];
                a[ii][2] = A[(kr + 4) * 132 + wm + ii * 16 + grp];
                a[ii][3] = A[(kr + 4) * 132 + wm + ii * 16 + grp + 8];
            }
            #pragma unroll
            for (int j = 0; j < 8; j++) {
                bf[j][0] = B[kr * 132       + wn + j * 8 + grp];
                bf[j][1] = B[(kr + 4) * 132 + wn + j * 8 + grp];
            }
            #pragma unroll
            for (int ii = 0; ii < 2; ii++)
                #pragma unroll
                for (int j = 0; j < 8; j++)
                    mma_tf32(acc[ii][j], a[ii], bf[j]);
        }

        if (i < 15) {
            sts_tile((i + 1) & 1);
            __syncthreads();
        }
    }

    #pragma unroll
    for (int i = 0; i < 2; i++) {
        #pragma unroll
        for (int r = 0; r < 2; r++) {
            int m = m0 + wm + i * 16 + grp + r * 8;
            float bias; float* dst;
            if (m < 64)        { bias = bq[m];        dst = g_q + ((size_t)b * C8 + m) * SS; }
            else if (m < 128)  { bias = bk[m - 64];   dst = g_k + ((size_t)b * C8 + m - 64) * SS; }
            else               { bias = bv[m - 128];  dst = g_v + ((size_t)b * CC + m - 128) * SS; }
            float* row = dst + n0 + wn + tig * 2;
            #pragma unroll
            for (int j = 0; j < 8; j++) {
                float2 o;
                o.x = acc[i][j][r * 2 + 0] + bias;
                o.y = acc[i][j][r * 2 + 1] + bias;
                *reinterpret_cast<float2*>(row + j * 8) = o;
            }
        }
    }
}

// ---------------- K2: plane transpose (w<->h), 128x128 planes ------------------
__global__ void transpose_wh(float* __restrict__ dst, const float* __restrict__ src) {
    __shared__ float t[32][33];
    const size_t base = (size_t)blockIdx.z * SS;
    const int x0 = blockIdx.x * 32, y0 = blockIdx.y * 32;
    const int tx = threadIdx.x, ty = threadIdx.y;
    #pragma unroll
    for (int i = 0; i < 32; i += 8)
        t[ty + i][tx] = src[base + (size_t)(y0 + ty + i) * S + x0 + tx];
    __syncthreads();
    #pragma unroll
    for (int i = 0; i < 32; i += 8)
        dst[base + (size_t)(x0 + ty + i) * S + y0 + tx] = t[tx][ty + i];
}

// ---------------- K3: attention logits, single-shot K=64 -----------------------
__global__ void __launch_bounds__(256, 2)
attn_logits_mma(const float* __restrict__ qsrc, const float* __restrict__ ksrc,
                float* __restrict__ att, int is_col) {
    extern __shared__ uint32_t sm[];   // Qs[64][132] | Ks[64][132]
    uint32_t* Qs = sm;
    uint32_t* Ks = sm + 64 * 132;

    const int p = blockIdx.x;
    const int b = blockIdx.y;
    const int tid  = threadIdx.x;
    const int lane = tid & 31, wid = tid >> 5;
    const int grp  = lane >> 2, tig = lane & 3;
    const int wm   = (wid >> 1) * 32;
    const int wn   = (wid & 1) * 64;

    const size_t qbase = (size_t)b * C8 * SS + (size_t)p * S;

    // load the whole K extent (64 c-rows) once
    #pragma unroll
    for (int l = 0; l < 8; l++) {
        int idx = l * 256 + tid;        // 2048 float4 slots: 64 c x 32 q4
        int cc  = idx >> 5;
        int nq  = idx & 31;
        size_t g = qbase + (size_t)cc * SS + nq * 4;
        float4 vq = *reinterpret_cast<const float4*>(qsrc + g);
        float4 vk = *reinterpret_cast<const float4*>(ksrc + g);
        Qs[cc * 132 + nq * 4 + 0] = f2tf32(vq.x);
        Qs[cc * 132 + nq * 4 + 1] = f2tf32(vq.y);
        Qs[cc * 132 + nq * 4 + 2] = f2tf32(vq.z);
        Qs[cc * 132 + nq * 4 + 3] = f2tf32(vq.w);
        Ks[cc * 132 + nq * 4 + 0] = f2tf32(vk.x);
        Ks[cc * 132 + nq * 4 + 1] = f2tf32(vk.y);
        Ks[cc * 132 + nq * 4 + 2] = f2tf32(vk.z);
        Ks[cc * 132 + nq * 4 + 3] = f2tf32(vk.w);
    }
    __syncthreads();

    float acc[2][8][4] = {};
    #pragma unroll
    for (int kk = 0; kk < 8; kk++) {
        const int kr = kk * 8 + tig;
        uint32_t a[2][4], bf[8][2];
        #pragma unroll
        for (int i = 0; i < 2; i++) {
            a[i][0] = Qs[kr * 132       + wm + i * 16 + grp];
            a[i][1] = Qs[kr * 132       + wm + i * 16 + grp + 8];
            a[i][2] = Qs[(kr + 4) * 132 + wm + i * 16 + grp];
            a[i][3] = Qs[(kr + 4) * 132 + wm + i * 16 + grp + 8];
        }
        #pragma unroll
        for (int j = 0; j < 8; j++) {
            bf[j][0] = Ks[kr * 132       + wn + j * 8 + grp];
            bf[j][1] = Ks[(kr + 4) * 132 + wn + j * 8 + grp];
        }
        #pragma unroll
        for (int i = 0; i < 2; i++)
            #pragma unroll
            for (int j = 0; j < 8; j++)
                mma_tf32(acc[i][j], a[i], bf[j]);
    }

    const size_t obase  = (size_t)b * SS * 256 +
                          (is_col ? (size_t)p * 256 : (size_t)p * S * 256 + 128);
    const size_t rstride = is_col ? (size_t)S * 256 : 256;
    #pragma unroll
    for (int i = 0; i < 2; i++) {
        #pragma unroll
        for (int r = 0; r < 2; r++) {
            int rr = wm + i * 16 + grp + r * 8;
            float* row = att + obase + (size_t)rr * rstride + wn + tig * 2;
            #pragma unroll
            for (int j = 0; j < 8; j++) {
                int u = wn + j * 8 + tig * 2;
                float2 o;
                o.x = (is_col && rr == u)     ? NEG_INF_F : acc[i][j][r * 2 + 0];
                o.y = (is_col && rr == u + 1) ? NEG_INF_F : acc[i][j][r * 2 + 1];
                *reinterpret_cast<float2*>(row + j * 8) = o;
            }
        }
    }
}

// ---------------- K4: softmax over 256, one warp per row -----------------------
__global__ void softmax256(float* __restrict__ att) {
    const int row  = blockIdx.x * 8 + (threadIdx.x >> 5);
    const int lane = threadIdx.x & 31;
    float* pr = att + (size_t)row * 256;

    float vals[8];
    float m = -3.4e38f;
    #pragma unroll
    for (int i = 0; i < 8; i++) { vals[i] = pr[lane + i * 32]; m = fmaxf(m, vals[i]); }
    #pragma unroll
    for (int o = 16; o > 0; o >>= 1) m = fmaxf(m, __shfl_xor_sync(0xffffffff, m, o));
    float s = 0.f;
    #pragma unroll
    for (int i = 0; i < 8; i++) { vals[i] = __expf(vals[i] - m); s += vals[i]; }
    #pragma unroll
    for (int o = 16; o > 0; o >>= 1) s += __shfl_xor_sync(0xffffffff, s, o);
    float inv = 1.f / s;
    #pragma unroll
    for (int i = 0; i < 8; i++) pr[lane + i * 32] = vals[i] * inv;
}

// ---------------- K5: attention @ V, pipelined; fused gamma (+x for row) -------
__global__ void __launch_bounds__(256, 2)
attn_av_mma(const float* __restrict__ vsrc, const float* __restrict__ att,
            float* __restrict__ dst, const float* __restrict__ gammap,
            const float* __restrict__ xres, int is_col) {
    extern __shared__ uint32_t sm[];   // [V0|T0|V1|T1], each TILE32 ([u][c]/[u][q])

    const int ct = blockIdx.x;
    const int p  = blockIdx.y;
    const int b  = blockIdx.z;
    const int tid  = threadIdx.x;
    const int lane = tid & 31, wid = tid >> 5;
    const int g8   = lane >> 2, tig = lane & 3;
    const int wm   = (wid >> 1) * 32;
    const int wn   = (wid & 1) * 64;

    const size_t vbase = (size_t)(b * CC + ct * 128) * SS + (size_t)p * S;
    const size_t abase = (size_t)b * SS * 256 +
                         (is_col ? (size_t)p * 256 : (size_t)p * S * 256 + 128);
    const size_t aq = is_col ? (size_t)S * 256 : 256;

    const float gm = gammap[0];

    float acc[2][8][4] = {};
    float4 pv[4], pt[4];

    auto ldg_tile = [&](int u0) {
        #pragma unroll
        for (int l = 0; l < 4; l++) {
            int idx = l * 256 + tid;
            int cp = idx >> 3, uq = idx & 7;
            pv[l] = *reinterpret_cast<const float4*>(
                vsrc + vbase + (size_t)cp * SS + u0 + uq * 4);
            pt[l] = *reinterpret_cast<const float4*>(
                att + abase + (size_t)cp * aq + u0 + uq * 4);
        }
    };
    auto sts_tile = [&](int buf) {
        uint32_t* V = sm + buf * 2 * TILE32;
        uint32_t* T = V + TILE32;
        #pragma unroll
        for (int l = 0; l < 4; l++) {
            int idx = l * 256 + tid;
            int cp = idx >> 3, uq = idx & 7;
            V[(uq * 4 + 0) * 132 + cp] = f2tf32(pv[l].x);
            V[(uq * 4 + 1) * 132 + cp] = f2tf32(pv[l].y);
            V[(uq * 4 + 2) * 132 + cp] = f2tf32(pv[l].z);
            V[(uq * 4 + 3) * 132 + cp] = f2tf32(pv[l].w);
            T[(uq * 4 + 0) * 132 + cp] = f2tf32(pt[l].x);
            T[(uq * 4 + 1) * 132 + cp] = f2tf32(pt[l].y);
            T[(uq * 4 + 2) * 132 + cp] = f2tf32(pt[l].z);
            T[(uq * 4 + 3) * 132 + cp] = f2tf32(pt[l].w);
        }
    };

    ldg_tile(0);
    sts_tile(0);
    __syncthreads();

    for (int i = 0; i < 4; i++) {
        if (i < 3) ldg_tile((i + 1) * 32);

        const uint32_t* V = sm + (i & 1) * 2 * TILE32;
        const uint32_t* T = V + TILE32;
        #pragma unroll
        for (int kk = 0; kk < 4; kk++) {
            const int kr = kk * 8 + tig;
            uint32_t a[2][4], bf[8][2];
            #pragma unroll
            for (int ii = 0; ii < 2; ii++) {
                a[ii][0] = V[kr * 132       + wm + ii * 16 + g8];
                a[ii][1] = V[kr * 132       + wm + ii * 16 + g8 + 8];
                a[ii][2] = V[(kr + 4) * 132 + wm + ii * 16 + g8];
                a[ii][3] = V[(kr + 4) * 132 + wm + ii * 16 + g8 + 8];
            }
            #pragma unroll
            for (int j = 0; j < 8; j++) {
                bf[j][0] = T[kr * 132       + wn + j * 8 + g8];
                bf[j][1] = T[(kr + 4) * 132 + wn + j * 8 + g8];
            }
            #pragma unroll
            for (int ii = 0; ii < 2; ii++)
                #pragma unroll
                for (int j = 0; j < 8; j++)
                    mma_tf32(acc[ii][j], a[ii], bf[j]);
        }

        if (i < 3) {
            sts_tile((i + 1) & 1);
            __syncthreads();
        }
    }

    // epilogue: col -> gm*acc to ocolT; row -> gm*acc + x to out
    #pragma unroll
    for (int i = 0; i < 2; i++) {
        #pragma unroll
        for (int r = 0; r < 2; r++) {
            int cl = wm + i * 16 + g8 + r * 8;
            size_t off = vbase + (size_t)cl * SS + wn + tig * 2;
            float* row = dst + off;
            if (is_col) {
                #pragma unroll
                for (int j = 0; j < 8; j++) {
                    float2 o;
                    o.x = gm * acc[i][j][r * 2 + 0];
                    o.y = gm * acc[i][j][r * 2 + 1];
                    *reinterpret_cast<float2*>(row + j * 8) = o;
                }
            } else {
                const float* xrow = xres + off;
                #pragma unroll
                for (int j = 0; j < 8; j++) {
                    float2 xr = *reinterpret_cast<const float2*>(xrow + j * 8);
                    float2 o;
                    o.x = gm * acc[i][j][r * 2 + 0] + xr.x;
                    o.y = gm * acc[i][j][r * 2 + 1] + xr.y;
                    *reinterpret_cast<float2*>(row + j * 8) = o;
                }
            }
        }
    }
}

// ---------------- K6: out += transpose(ocolT)  (gamma, x already applied) ------
__global__ void final_combine(const float* __restrict__ ocolT, float* __restrict__ out) {
    __shared__ float t[32][33];
    const size_t base = (size_t)blockIdx.z * SS;
    const int w0 = blockIdx.x * 32, h0 = blockIdx.y * 32;
    const int tx = threadIdx.x, ty = threadIdx.y;
    #pragma unroll
    for (int i = 0; i < 32; i += 8)
        t[ty + i][tx] = ocolT[base + (size_t)(h0 + ty + i) * S + w0 + tx];
    __syncthreads();
    #pragma unroll
    for (int i = 0; i < 32; i += 8) {
        size_t o = base + (size_t)(w0 + ty + i) * S + h0 + tx;
        out[o] = out[o] + t[tx][ty + i];
    }
}

// ---------------- launch ------------------------------------------------------
#define GEMM_SMEM 67584   // 4 * 32*132 * 4B  (== 2 * 64*132 * 4B)

extern "C" void kernel_launch(void* const* d_in, const int* in_sizes, int n_in,
                              void* d_out, int out_size) {
    const float* x     = (const float*)d_in[0];
    const float* Wq    = (const float*)d_in[1];
    const float* bq    = (const float*)d_in[2];
    const float* Wk    = (const float*)d_in[3];
    const float* bk    = (const float*)d_in[4];
    const float* Wv    = (const float*)d_in[5];
    const float* bv    = (const float*)d_in[6];
    const float* gamma = (const float*)d_in[7];
    float* out = (float*)d_out;

    float *q, *k, *qT, *kT, *v, *vT, *att, *ocolT;
    cudaGetSymbolAddress((void**)&q,     g_q);
    cudaGetSymbolAddress((void**)&k,     g_k);
    cudaGetSymbolAddress((void**)&qT,    g_qT);
    cudaGetSymbolAddress((void**)&kT,    g_kT);
    cudaGetSymbolAddress((void**)&v,     g_v);
    cudaGetSymbolAddress((void**)&vT,    g_vT);
    cudaGetSymbolAddress((void**)&att,   g_att);
    cudaGetSymbolAddress((void**)&ocolT, g_ocolT);

    static bool attr_done = false;
    if (!attr_done) {
        cudaFuncSetAttribute(qkv_gemm_mma,    cudaFuncAttributeMaxDynamicSharedMemorySize, GEMM_SMEM);
        cudaFuncSetAttribute(attn_logits_mma, cudaFuncAttributeMaxDynamicSharedMemorySize, GEMM_SMEM);
        cudaFuncSetAttribute(attn_av_mma,     cudaFuncAttributeMaxDynamicSharedMemorySize, GEMM_SMEM);
        attr_done = true;
    }

    // 1. QKV projection (tensor cores, pipelined)
    qkv_gemm_mma<<<dim3(5, NPIX / 128, BB), 256, GEMM_SMEM>>>(x, Wq, bq, Wk, bk, Wv, bv);

    // 2. transposes (w<->h)
    transpose_wh<<<dim3(4, 4, BB * C8), dim3(32, 8)>>>(qT, q);
    transpose_wh<<<dim3(4, 4, BB * C8), dim3(32, 8)>>>(kT, k);
    transpose_wh<<<dim3(4, 4, BB * CC), dim3(32, 8)>>>(vT, v);

    // 3. logits (tensor cores, single-shot K=64)
    attn_logits_mma<<<dim3(S, BB), 256, GEMM_SMEM>>>(qT, kT, att, 1);
    attn_logits_mma<<<dim3(S, BB), 256, GEMM_SMEM>>>(q,  k,  att, 0);

    // 4. softmax
    softmax256<<<(BB * SS) / 8, 256>>>(att);

    // 5. attention @ V (tensor cores, pipelined; gamma/x fused)
    attn_av_mma<<<dim3(4, S, BB), 256, GEMM_SMEM>>>(vT, att, ocolT, gamma, nullptr, 1);
    attn_av_mma<<<dim3(4, S, BB), 256, GEMM_SMEM>>>(v,  att, out,   gamma, x,       0);

    // 6. combine: out += ocolT^T
    final_combine<<<dim3(4, 4, BB * CC), dim3(32, 8)>>>(ocolT, out);
}

// round 6
// speedup vs baseline: 4.4925x; 1.2435x over previous
#include <cuda_runtime.h>
#include <cuda_bf16.h>
#include <cstdint>

#define BB 8
#define CC 512
#define C8 64
#define S  128
#define SS (S*S)
#define NPIX (SS)
#define NEG_INF_F (-1000000000.0f)

// ---------------- scratch buffers (device globals; no allocation) ----------------
__device__ float  g_q    [BB * C8 * SS];
__device__ float  g_k    [BB * C8 * SS];
__device__ float  g_qT   [BB * C8 * SS];
__device__ float  g_kT   [BB * C8 * SS];
__device__ float  g_v    [BB * CC * SS];
__device__ float  g_vT   [BB * CC * SS];
__device__ float  g_att  [BB * SS * 2 * S];
__device__ float  g_ocolT[BB * CC * SS];
__device__ float2 g_stat_col[BB * SS];
__device__ float2 g_stat_row[BB * SS];
__device__ float  g_scale_col[BB * SS];
__device__ float  g_scale_row[BB * SS];

// ---------------- mma.sync tf32 helpers ----------------------------------------
__device__ __forceinline__ uint32_t f2tf32(float f) {
    uint32_t u;
    asm("cvt.rn.tf32.f32 %0, %1;" : "=r"(u) : "f"(f));
    return u;
}
__device__ __forceinline__ uint4 tf32x4(float4 v) {
    return make_uint4(f2tf32(v.x), f2tf32(v.y), f2tf32(v.z), f2tf32(v.w));
}
__device__ __forceinline__ void mma_tf32(float c[4], const uint32_t a[4], const uint32_t b[2]) {
    asm volatile(
        "mma.sync.aligned.m16n8k8.row.col.f32.tf32.tf32.f32 "
        "{%0,%1,%2,%3}, {%4,%5,%6,%7}, {%8,%9}, {%0,%1,%2,%3};"
        : "+f"(c[0]), "+f"(c[1]), "+f"(c[2]), "+f"(c[3])
        : "r"(a[0]), "r"(a[1]), "r"(a[2]), "r"(a[3]), "r"(b[0]), "r"(b[1]));
}

// SMEM geometry (in 32-bit words)
#define PA   36      // [row][32k] tiles: pad 36  -> frag bank grp*4+tig (distinct), STS.128 ok
#define PB   136     // [32k][128n] tiles: pad 136 -> frag bank tig*8+grp (distinct), STS.128 ok
#define QKV_A_W   (128 * PA)          // 4608
#define QKV_B_W   (32 * PB)           // 4352
#define QKV_BUF_W (QKV_A_W + QKV_B_W) // 8960
#define QKV_SMEM  (2 * QKV_BUF_W * 4) // 71680 B
#define LG_Q_W    (64 * PB)           // 8704
#define LOGITS_SMEM (2 * LG_Q_W * 4)  // 69632 B
#define AV_V_W    (256 * PA)          // 9216
#define AV_T_W    (128 * PA)          // 4608
#define AV_BUF_W  (AV_V_W + AV_T_W)   // 13824
#define AV_SMEM   (2 * AV_BUF_W * 4)  // 110592 B

// ---------------- K1: QKV projection, pipelined, conflict-free SMEM -------------
__global__ void __launch_bounds__(256, 2)
qkv_gemm_mma(const float* __restrict__ x,
             const float* __restrict__ Wq, const float* __restrict__ bq,
             const float* __restrict__ Wk, const float* __restrict__ bk,
             const float* __restrict__ Wv, const float* __restrict__ bv) {
    extern __shared__ uint32_t sm[];

    const int tid  = threadIdx.x;
    const int lane = tid & 31, wid = tid >> 5;
    const int grp  = lane >> 2, tig = lane & 3;
    const int wm   = (wid >> 1) * 32;
    const int wn   = (wid & 1) * 64;
    const int m0   = blockIdx.x * 128;
    const int n0   = blockIdx.y * 128;
    const int b    = blockIdx.z;

    const float* xb = x + (size_t)b * CC * NPIX;

    float acc[2][8][4] = {};
    float4 pa[4], pb[4];

    auto ldg_tile = [&](int k0) {
        #pragma unroll
        for (int l = 0; l < 4; l++) {
            int idx = l * 256 + tid;
            int m = idx >> 3, kq = idx & 7;
            int mm = m0 + m;
            const float* src;
            if (mm < 64)        src = Wq + (size_t)mm * CC;
            else if (mm < 128)  src = Wk + (size_t)(mm - 64) * CC;
            else                src = Wv + (size_t)(mm - 128) * CC;
            pa[l] = *reinterpret_cast<const float4*>(src + k0 + kq * 4);
        }
        #pragma unroll
        for (int l = 0; l < 4; l++) {
            int idx = l * 256 + tid;
            int kk = idx >> 5, nq = idx & 31;
            pb[l] = *reinterpret_cast<const float4*>(
                xb + (size_t)(k0 + kk) * NPIX + n0 + nq * 4);
        }
    };
    auto sts_tile = [&](int buf) {
        uint32_t* A = sm + buf * QKV_BUF_W;          // [m][k] pad PA
        uint32_t* B = A + QKV_A_W;                   // [k][n] pad PB
        #pragma unroll
        for (int l = 0; l < 4; l++) {
            int idx = l * 256 + tid;
            int m = idx >> 3, kq = idx & 7;
            *reinterpret_cast<uint4*>(A + m * PA + kq * 4) = tf32x4(pa[l]);
        }
        #pragma unroll
        for (int l = 0; l < 4; l++) {
            int idx = l * 256 + tid;
            int kk = idx >> 5, nq = idx & 31;
            *reinterpret_cast<uint4*>(B + kk * PB + nq * 4) = tf32x4(pb[l]);
        }
    };

    ldg_tile(0);
    sts_tile(0);
    __syncthreads();

    for (int i = 0; i < 16; i++) {
        if (i < 15) ldg_tile((i + 1) * 32);

        const uint32_t* A = sm + (i & 1) * QKV_BUF_W;
        const uint32_t* B = A + QKV_A_W;
        #pragma unroll
        for (int kk = 0; kk < 4; kk++) {
            const int kr = kk * 8 + tig;
            uint32_t a[2][4], bf[8][2];
            #pragma unroll
            for (int ii = 0; ii < 2; ii++) {
                a[ii][0] = A[(wm + ii * 16 + grp    ) * PA + kr];
                a[ii][1] = A[(wm + ii * 16 + grp + 8) * PA + kr];
                a[ii][2] = A[(wm + ii * 16 + grp    ) * PA + kr + 4];
                a[ii][3] = A[(wm + ii * 16 + grp + 8) * PA + kr + 4];
            }
            #pragma unroll
            for (int j = 0; j < 8; j++) {
                bf[j][0] = B[kr * PB       + wn + j * 8 + grp];
                bf[j][1] = B[(kr + 4) * PB + wn + j * 8 + grp];
            }
            #pragma unroll
            for (int ii = 0; ii < 2; ii++)
                #pragma unroll
                for (int j = 0; j < 8; j++)
                    mma_tf32(acc[ii][j], a[ii], bf[j]);
        }

        if (i < 15) {
            sts_tile((i + 1) & 1);
            __syncthreads();
        }
    }

    #pragma unroll
    for (int i = 0; i < 2; i++) {
        #pragma unroll
        for (int r = 0; r < 2; r++) {
            int m = m0 + wm + i * 16 + grp + r * 8;
            float bias; float* dst;
            if (m < 64)        { bias = bq[m];        dst = g_q + ((size_t)b * C8 + m) * SS; }
            else if (m < 128)  { bias = bk[m - 64];   dst = g_k + ((size_t)b * C8 + m - 64) * SS; }
            else               { bias = bv[m - 128];  dst = g_v + ((size_t)b * CC + m - 128) * SS; }
            float* row = dst + n0 + wn + tig * 2;
            #pragma unroll
            for (int j = 0; j < 8; j++) {
                float2 o;
                o.x = acc[i][j][r * 2 + 0] + bias;
                o.y = acc[i][j][r * 2 + 1] + bias;
                *reinterpret_cast<float2*>(row + j * 8) = o;
            }
        }
    }
}

// ---------------- K2: plane transpose (w<->h), 128x128 planes ------------------
__global__ void transpose_wh(float* __restrict__ dst, const float* __restrict__ src) {
    __shared__ float t[32][33];
    const size_t base = (size_t)blockIdx.z * SS;
    const int x0 = blockIdx.x * 32, y0 = blockIdx.y * 32;
    const int tx = threadIdx.x, ty = threadIdx.y;
    #pragma unroll
    for (int i = 0; i < 32; i += 8)
        t[ty + i][tx] = src[base + (size_t)(y0 + ty + i) * S + x0 + tx];
    __syncthreads();
    #pragma unroll
    for (int i = 0; i < 32; i += 8)
        dst[base + (size_t)(x0 + ty + i) * S + y0 + tx] = t[tx][ty + i];
}

// ---------------- K3: logits + unnormalized exp + per-row (m,s) stats ----------
__global__ void __launch_bounds__(256, 2)
attn_logits_mma(const float* __restrict__ qsrc, const float* __restrict__ ksrc,
                float* __restrict__ att, float2* __restrict__ stat, int is_col) {
    extern __shared__ uint32_t sm[];
    uint32_t* Qs = sm;              // [c][pixel] pad PB
    uint32_t* Ks = sm + LG_Q_W;
    __shared__ float redm[128][2];
    __shared__ float reds[128][2];

    const int p = blockIdx.x;
    const int b = blockIdx.y;
    const int tid  = threadIdx.x;
    const int lane = tid & 31, wid = tid >> 5;
    const int grp  = lane >> 2, tig = lane & 3;
    const int wm   = (wid >> 1) * 32;
    const int wc   = wid & 1;
    const int wn   = wc * 64;

    const size_t qbase = (size_t)b * C8 * SS + (size_t)p * S;

    #pragma unroll
    for (int l = 0; l < 8; l++) {
        int idx = l * 256 + tid;
        int cc  = idx >> 5;
        int nq  = idx & 31;
        size_t g = qbase + (size_t)cc * SS + nq * 4;
        *reinterpret_cast<uint4*>(Qs + cc * PB + nq * 4) =
            tf32x4(*reinterpret_cast<const float4*>(qsrc + g));
        *reinterpret_cast<uint4*>(Ks + cc * PB + nq * 4) =
            tf32x4(*reinterpret_cast<const float4*>(ksrc + g));
    }
    __syncthreads();

    float acc[2][8][4] = {};
    #pragma unroll
    for (int kk = 0; kk < 8; kk++) {
        const int kr = kk * 8 + tig;
        uint32_t a[2][4], bf[8][2];
        #pragma unroll
        for (int i = 0; i < 2; i++) {
            a[i][0] = Qs[kr * PB       + wm + i * 16 + grp];
            a[i][1] = Qs[kr * PB       + wm + i * 16 + grp + 8];
            a[i][2] = Qs[(kr + 4) * PB + wm + i * 16 + grp];
            a[i][3] = Qs[(kr + 4) * PB + wm + i * 16 + grp + 8];
        }
        #pragma unroll
        for (int j = 0; j < 8; j++) {
            bf[j][0] = Ks[kr * PB       + wn + j * 8 + grp];
            bf[j][1] = Ks[(kr + 4) * PB + wn + j * 8 + grp];
        }
        #pragma unroll
        for (int i = 0; i < 2; i++)
            #pragma unroll
            for (int j = 0; j < 8; j++)
                mma_tf32(acc[i][j], a[i], bf[j]);
    }

    // diag mask (col half only)
    if (is_col) {
        #pragma unroll
        for (int i = 0; i < 2; i++)
            #pragma unroll
            for (int r = 0; r < 2; r++) {
                int rr = wm + i * 16 + grp + r * 8;
                #pragma unroll
                for (int j = 0; j < 8; j++) {
                    int u = wn + j * 8 + tig * 2;
                    if (rr == u)     acc[i][j][r * 2 + 0] = NEG_INF_F;
                    if (rr == u + 1) acc[i][j][r * 2 + 1] = NEG_INF_F;
                }
            }
    }

    // row max (over 128 cols): intra-quartet shfl, then cross warp-pair via smem
    float mloc[2][2];
    #pragma unroll
    for (int i = 0; i < 2; i++)
        #pragma unroll
        for (int r = 0; r < 2; r++) {
            float ml = -3.4e38f;
            #pragma unroll
            for (int j = 0; j < 8; j++) {
                ml = fmaxf(ml, acc[i][j][r * 2 + 0]);
                ml = fmaxf(ml, acc[i][j][r * 2 + 1]);
            }
            ml = fmaxf(ml, __shfl_xor_sync(0xffffffff, ml, 1));
            ml = fmaxf(ml, __shfl_xor_sync(0xffffffff, ml, 2));
            mloc[i][r] = ml;
        }
    if (tig == 0) {
        #pragma unroll
        for (int i = 0; i < 2; i++)
            #pragma unroll
            for (int r = 0; r < 2; r++)
                redm[wm + i * 16 + grp + r * 8][wc] = mloc[i][r];
    }
    __syncthreads();

    float mrow[2][2], sloc[2][2];
    #pragma unroll
    for (int i = 0; i < 2; i++)
        #pragma unroll
        for (int r = 0; r < 2; r++) {
            int rr = wm + i * 16 + grp + r * 8;
            float m = fmaxf(redm[rr][0], redm[rr][1]);
            mrow[i][r] = m;
            float sl = 0.f;
            #pragma unroll
            for (int j = 0; j < 8; j++) {
                float e0 = __expf(acc[i][j][r * 2 + 0] - m);
                float e1 = __expf(acc[i][j][r * 2 + 1] - m);
                acc[i][j][r * 2 + 0] = e0;
                acc[i][j][r * 2 + 1] = e1;
                sl += e0 + e1;
            }
            sl += __shfl_xor_sync(0xffffffff, sl, 1);
            sl += __shfl_xor_sync(0xffffffff, sl, 2);
            sloc[i][r] = sl;
        }
    if (tig == 0) {
        #pragma unroll
        for (int i = 0; i < 2; i++)
            #pragma unroll
            for (int r = 0; r < 2; r++)
                reds[wm + i * 16 + grp + r * 8][wc] = sloc[i][r];
    }
    __syncthreads();

    if (tig == 0 && wc == 0) {
        #pragma unroll
        for (int i = 0; i < 2; i++)
            #pragma unroll
            for (int r = 0; r < 2; r++) {
                int rr = wm + i * 16 + grp + r * 8;
                stat[(size_t)b * SS + (size_t)p * S + rr] =
                    make_float2(mrow[i][r], reds[rr][0] + reds[rr][1]);
            }
    }

    // store exp values
    const size_t obase  = (size_t)b * SS * 256 +
                          (is_col ? (size_t)p * 256 : (size_t)p * S * 256 + 128);
    const size_t rstride = is_col ? (size_t)S * 256 : 256;
    #pragma unroll
    for (int i = 0; i < 2; i++) {
        #pragma unroll
        for (int r = 0; r < 2; r++) {
            int rr = wm + i * 16 + grp + r * 8;
            float* row = att + obase + (size_t)rr * rstride + wn + tig * 2;
            #pragma unroll
            for (int j = 0; j < 8; j++) {
                float2 o;
                o.x = acc[i][j][r * 2 + 0];
                o.y = acc[i][j][r * 2 + 1];
                *reinterpret_cast<float2*>(row + j * 8) = o;
            }
        }
    }
}

// ---------------- K4: combine halves -> per-pixel normalization scales ---------
__global__ void softmax_combine(const float2* __restrict__ sc, const float2* __restrict__ sr,
                                float* __restrict__ scol, float* __restrict__ srow) {
    const int b = blockIdx.y;
    const int t = blockIdx.x * 256 + threadIdx.x;   // col-layout index: h*S + w
    const int w = t & (S - 1), h = t >> 7;
    float2 c = sc[(size_t)b * SS + t];
    float2 r = sr[(size_t)b * SS + w * S + h];
    float m  = fmaxf(c.x, r.x);
    float ec = __expf(c.x - m), er = __expf(r.x - m);
    float inv = 1.f / (c.y * ec + r.y * er);
    scol[(size_t)b * SS + t]         = ec * inv;
    srow[(size_t)b * SS + w * S + h] = er * inv;
}

// ---------------- K5: attention @ V, M=256, fused gamma*scale (+x for row) -----
__global__ void __launch_bounds__(512, 1)
attn_av_mma(const float* __restrict__ vsrc, const float* __restrict__ att,
            float* __restrict__ dst, const float* __restrict__ gammap,
            const float* __restrict__ xres, const float* __restrict__ scale,
            int is_col) {
    extern __shared__ uint32_t sm[];

    const int ct = blockIdx.x;        // 0..1 (c tile of 256)
    const int p  = blockIdx.y;
    const int b  = blockIdx.z;
    const int tid  = threadIdx.x;
    const int lane = tid & 31, wid = tid >> 5;      // wid 0..15
    const int grp  = lane >> 2, tig = lane & 3;
    const int wm   = (wid >> 1) * 32;               // 0..224
    const int wn   = (wid & 1) * 64;

    const size_t vbase = (size_t)(b * CC + ct * 256) * SS + (size_t)p * S;
    const size_t abase = (size_t)b * SS * 256 +
                         (is_col ? (size_t)p * 256 : (size_t)p * S * 256 + 128);
    const size_t aq = is_col ? (size_t)S * 256 : 256;

    const float gm = gammap[0];

    float acc[2][8][4] = {};
    float4 pv[4], pt[2];

    auto ldg_tile = [&](int u0) {
        #pragma unroll
        for (int l = 0; l < 4; l++) {
            int idx = l * 512 + tid;
            int cp = idx >> 3, uq = idx & 7;        // cp 0..255
            pv[l] = *reinterpret_cast<const float4*>(
                vsrc + vbase + (size_t)cp * SS + u0 + uq * 4);
        }
        #pragma unroll
        for (int l = 0; l < 2; l++) {
            int idx = l * 512 + tid;
            int qp = idx >> 3, uq = idx & 7;        // qp 0..127
            pt[l] = *reinterpret_cast<const float4*>(
                att + abase + (size_t)qp * aq + u0 + uq * 4);
        }
    };
    auto sts_tile = [&](int buf) {
        uint32_t* V = sm + buf * AV_BUF_W;          // [c][u] pad PA
        uint32_t* T = V + AV_V_W;                   // [q][u] pad PA
        #pragma unroll
        for (int l = 0; l < 4; l++) {
            int idx = l * 512 + tid;
            int cp = idx >> 3, uq = idx & 7;
            *reinterpret_cast<uint4*>(V + cp * PA + uq * 4) = tf32x4(pv[l]);
        }
        #pragma unroll
        for (int l = 0; l < 2; l++) {
            int idx = l * 512 + tid;
            int qp = idx >> 3, uq = idx & 7;
            *reinterpret_cast<uint4*>(T + qp * PA + uq * 4) = tf32x4(pt[l]);
        }
    };

    ldg_tile(0);
    sts_tile(0);
    __syncthreads();

    for (int i = 0; i < 4; i++) {
        if (i < 3) ldg_tile((i + 1) * 32);

        const uint32_t* V = sm + (i & 1) * AV_BUF_W;
        const uint32_t* T = V + AV_V_W;
        #pragma unroll
        for (int kk = 0; kk < 4; kk++) {
            const int kr = kk * 8 + tig;
            uint32_t a[2][4], bf[8][2];
            #pragma unroll
            for (int ii = 0; ii < 2; ii++) {
                a[ii][0] = V[(wm + ii * 16 + grp    ) * PA + kr];
                a[ii][1] = V[(wm + ii * 16 + grp + 8) * PA + kr];
                a[ii][2] = V[(wm + ii * 16 + grp    ) * PA + kr + 4];
                a[ii][3] = V[(wm + ii * 16 + grp + 8) * PA + kr + 4];
            }
            #pragma unroll
            for (int j = 0; j < 8; j++) {
                bf[j][0] = T[(wn + j * 8 + grp) * PA + kr];
                bf[j][1] = T[(wn + j * 8 + grp) * PA + kr + 4];
            }
            #pragma unroll
            for (int ii = 0; ii < 2; ii++)
                #pragma unroll
                for (int j = 0; j < 8; j++)
                    mma_tf32(acc[ii][j], a[ii], bf[j]);
        }

        if (i < 3) {
            sts_tile((i + 1) & 1);
            __syncthreads();
        }
    }

    // per-q normalization scales (column q of O tile)
    const float* scl = scale + (size_t)b * SS + (size_t)p * S;
    float2 scv[8];
    #pragma unroll
    for (int j = 0; j < 8; j++)
        scv[j] = *reinterpret_cast<const float2*>(scl + wn + j * 8 + tig * 2);

    #pragma unroll
    for (int i = 0; i < 2; i++) {
        #pragma unroll
        for (int r = 0; r < 2; r++) {
            int cl = wm + i * 16 + grp + r * 8;
            size_t off = vbase + (size_t)cl * SS + wn + tig * 2;
            float* row = dst + off;
            if (is_col) {
                #pragma unroll
                for (int j = 0; j < 8; j++) {
                    float2 o;
                    o.x = gm * scv[j].x * acc[i][j][r * 2 + 0];
                    o.y = gm * scv[j].y * acc[i][j][r * 2 + 1];
                    *reinterpret_cast<float2*>(row + j * 8) = o;
                }
            } else {
                const float* xrow = xres + off;
                #pragma unroll
                for (int j = 0; j < 8; j++) {
                    float2 xr = *reinterpret_cast<const float2*>(xrow + j * 8);
                    float2 o;
                    o.x = gm * scv[j].x * acc[i][j][r * 2 + 0] + xr.x;
                    o.y = gm * scv[j].y * acc[i][j][r * 2 + 1] + xr.y;
                    *reinterpret_cast<float2*>(row + j * 8) = o;
                }
            }
        }
    }
}

// ---------------- K6: out += transpose(ocolT) ----------------------------------
__global__ void final_combine(const float* __restrict__ ocolT, float* __restrict__ out) {
    __shared__ float t[32][33];
    const size_t base = (size_t)blockIdx.z * SS;
    const int w0 = blockIdx.x * 32, h0 = blockIdx.y * 32;
    const int tx = threadIdx.x, ty = threadIdx.y;
    #pragma unroll
    for (int i = 0; i < 32; i += 8)
        t[ty + i][tx] = ocolT[base + (size_t)(h0 + ty + i) * S + w0 + tx];
    __syncthreads();
    #pragma unroll
    for (int i = 0; i < 32; i += 8) {
        size_t o = base + (size_t)(w0 + ty + i) * S + h0 + tx;
        out[o] = out[o] + t[tx][ty + i];
    }
}

// ---------------- launch ------------------------------------------------------
extern "C" void kernel_launch(void* const* d_in, const int* in_sizes, int n_in,
                              void* d_out, int out_size) {
    const float* x     = (const float*)d_in[0];
    const float* Wq    = (const float*)d_in[1];
    const float* bq    = (const float*)d_in[2];
    const float* Wk    = (const float*)d_in[3];
    const float* bk    = (const float*)d_in[4];
    const float* Wv    = (const float*)d_in[5];
    const float* bv    = (const float*)d_in[6];
    const float* gamma = (const float*)d_in[7];
    float* out = (float*)d_out;

    float *q, *k, *qT, *kT, *v, *vT, *att, *ocolT, *scol, *srow;
    float2 *stc, *str;
    cudaGetSymbolAddress((void**)&q,     g_q);
    cudaGetSymbolAddress((void**)&k,     g_k);
    cudaGetSymbolAddress((void**)&qT,    g_qT);
    cudaGetSymbolAddress((void**)&kT,    g_kT);
    cudaGetSymbolAddress((void**)&v,     g_v);
    cudaGetSymbolAddress((void**)&vT,    g_vT);
    cudaGetSymbolAddress((void**)&att,   g_att);
    cudaGetSymbolAddress((void**)&ocolT, g_ocolT);
    cudaGetSymbolAddress((void**)&stc,   g_stat_col);
    cudaGetSymbolAddress((void**)&str,   g_stat_row);
    cudaGetSymbolAddress((void**)&scol,  g_scale_col);
    cudaGetSymbolAddress((void**)&srow,  g_scale_row);

    static bool attr_done = false;
    if (!attr_done) {
        cudaFuncSetAttribute(qkv_gemm_mma,    cudaFuncAttributeMaxDynamicSharedMemorySize, QKV_SMEM);
        cudaFuncSetAttribute(attn_logits_mma, cudaFuncAttributeMaxDynamicSharedMemorySize, LOGITS_SMEM);
        cudaFuncSetAttribute(attn_av_mma,     cudaFuncAttributeMaxDynamicSharedMemorySize, AV_SMEM);
        attr_done = true;
    }

    // 1. QKV projection
    qkv_gemm_mma<<<dim3(5, NPIX / 128, BB), 256, QKV_SMEM>>>(x, Wq, bq, Wk, bk, Wv, bv);

    // 2. transposes (w<->h)
    transpose_wh<<<dim3(4, 4, BB * C8), dim3(32, 8)>>>(qT, q);
    transpose_wh<<<dim3(4, 4, BB * C8), dim3(32, 8)>>>(kT, k);
    transpose_wh<<<dim3(4, 4, BB * CC), dim3(32, 8)>>>(vT, v);

    // 3. logits -> exp(e - m_half) + per-row stats
    attn_logits_mma<<<dim3(S, BB), 256, LOGITS_SMEM>>>(qT, kT, att, stc, 1);
    attn_logits_mma<<<dim3(S, BB), 256, LOGITS_SMEM>>>(q,  k,  att, str, 0);

    // 4. combine halves -> normalization scales
    softmax_combine<<<dim3(SS / 256, BB), 256>>>(stc, str, scol, srow);

    // 5. attention @ V (M=256, gamma*scale fused; row adds x)
    attn_av_mma<<<dim3(2, S, BB), 512, AV_SMEM>>>(vT, att, ocolT, gamma, nullptr, scol, 1);
    attn_av_mma<<<dim3(2, S, BB), 512, AV_SMEM>>>(v,  att, out,   gamma, x,       srow, 0);

    // 6. combine: out += ocolT^T
    final_combine<<<dim3(4, 4, BB * CC), dim3(32, 8)>>>(ocolT, out);
}